// round 1
// baseline (speedup 1.0000x reference)
#include <cuda_runtime.h>
#include <cuda_bf16.h>

// Problem constants
#define NROWS 4096
#define NF    256
#define NH    4

#define K1_BLOCKS 128   // 32 rows each, 8 warps -> 4 rows/warp
#define K3_BLOCKS 128   // 32 rows each
#define ROWS_PER_K3 (NROWS / K3_BLOCKS)   // 32

// Scratch (allocation-free rule: __device__ globals)
__device__ float g_e[NROWS * NH];          // exp(scores), 64 KB
__device__ float g_part[K3_BLOCKS * NF];   // per-block partial weighted sums
__device__ float g_cf[NF];                 // final broadcast row

// ---------------------------------------------------------------------------
// K1: e[j,h] = exp( dot(x[j,:], W[h, 256:512]) )
// One row per warp; W2 staged in smem as float4.
// ---------------------------------------------------------------------------
__global__ void k1_scores(const float* __restrict__ x, const float* __restrict__ W) {
    __shared__ float4 w2[NH][NF / 4];   // 4 KB

    const int tid = threadIdx.x;        // 256 threads
    // Load W2: W[h*512 + 256 + k], vectorize by float4 (offset 256 is 16B-aligned)
    for (int i = tid; i < NH * (NF / 4); i += 256) {
        int h = i / (NF / 4);
        int k4 = i % (NF / 4);
        w2[h][k4] = reinterpret_cast<const float4*>(W + h * 2 * NF + NF)[k4];
    }
    __syncthreads();

    const int warp = tid >> 5, lane = tid & 31;
    const int base = blockIdx.x * (NROWS / K1_BLOCKS);   // 32 rows per block

    for (int r = warp; r < NROWS / K1_BLOCKS; r += 8) {
        const int j = base + r;
        const float4* xr = reinterpret_cast<const float4*>(x + (size_t)j * NF);
        float a0 = 0.f, a1 = 0.f, a2 = 0.f, a3 = 0.f;
        #pragma unroll
        for (int t = 0; t < 2; ++t) {
            const int k4 = lane + t * 32;     // 64 float4 per row
            const float4 xv = xr[k4];
            float4 w;
            w = w2[0][k4]; a0 += xv.x * w.x + xv.y * w.y + xv.z * w.z + xv.w * w.w;
            w = w2[1][k4]; a1 += xv.x * w.x + xv.y * w.y + xv.z * w.z + xv.w * w.w;
            w = w2[2][k4]; a2 += xv.x * w.x + xv.y * w.y + xv.z * w.z + xv.w * w.w;
            w = w2[3][k4]; a3 += xv.x * w.x + xv.y * w.y + xv.z * w.z + xv.w * w.w;
        }
        #pragma unroll
        for (int o = 16; o; o >>= 1) {
            a0 += __shfl_xor_sync(0xffffffffu, a0, o);
            a1 += __shfl_xor_sync(0xffffffffu, a1, o);
            a2 += __shfl_xor_sync(0xffffffffu, a2, o);
            a3 += __shfl_xor_sync(0xffffffffu, a3, o);
        }
        if (lane == 0) {
            // No max-subtraction: scores ~ N(0, 0.16); exp is safe in fp32,
            // and softmax is shift-invariant so result matches the reference.
            float4 e4 = make_float4(expf(a0), expf(a1), expf(a2), expf(a3));
            reinterpret_cast<float4*>(g_e)[j] = e4;
        }
    }
}

// ---------------------------------------------------------------------------
// K3: each block (redundantly, deterministically) reduces d[h] = sum_j e[j,h],
// forms u[j] = sum_h e[j,h] / (H * d[h]) for its 32 rows, then accumulates
// partial c[f] = sum_{j in chunk} u[j] * x[j,f].
// ---------------------------------------------------------------------------
__global__ void k3_partial(const float* __restrict__ x) {
    const int tid = threadIdx.x;        // 256 threads
    const int lane = tid & 31, warp = tid >> 5;

    // --- full reduction of g_e (fixed order -> deterministic) ---
    float d0 = 0.f, d1 = 0.f, d2 = 0.f, d3 = 0.f;
    #pragma unroll 4
    for (int j = tid; j < NROWS; j += 256) {
        float4 e = reinterpret_cast<const float4*>(g_e)[j];
        d0 += e.x; d1 += e.y; d2 += e.z; d3 += e.w;
    }
    #pragma unroll
    for (int o = 16; o; o >>= 1) {
        d0 += __shfl_xor_sync(0xffffffffu, d0, o);
        d1 += __shfl_xor_sync(0xffffffffu, d1, o);
        d2 += __shfl_xor_sync(0xffffffffu, d2, o);
        d3 += __shfl_xor_sync(0xffffffffu, d3, o);
    }
    __shared__ float red[8][NH];
    if (lane == 0) { red[warp][0] = d0; red[warp][1] = d1; red[warp][2] = d2; red[warp][3] = d3; }
    __syncthreads();

    __shared__ float inv[NH];
    if (tid == 0) {
        #pragma unroll
        for (int h = 0; h < NH; ++h) {
            float s = 0.f;
            #pragma unroll
            for (int w = 0; w < 8; ++w) s += red[w][h];
            inv[h] = 1.0f / ((float)NH * s);
        }
    }
    __syncthreads();

    // --- per-row combined weight u[j] for this block's chunk ---
    __shared__ float u[ROWS_PER_K3];
    const int base = blockIdx.x * ROWS_PER_K3;
    if (tid < ROWS_PER_K3) {
        float4 e = reinterpret_cast<const float4*>(g_e)[base + tid];
        u[tid] = e.x * inv[0] + e.y * inv[1] + e.z * inv[2] + e.w * inv[3];
    }
    __syncthreads();

    // --- partial weighted column sum: thread tid owns column f = tid ---
    float acc0 = 0.f, acc1 = 0.f, acc2 = 0.f, acc3 = 0.f;
    #pragma unroll
    for (int r = 0; r < ROWS_PER_K3; r += 4) {
        acc0 += u[r + 0] * x[(size_t)(base + r + 0) * NF + tid];
        acc1 += u[r + 1] * x[(size_t)(base + r + 1) * NF + tid];
        acc2 += u[r + 2] * x[(size_t)(base + r + 2) * NF + tid];
        acc3 += u[r + 3] * x[(size_t)(base + r + 3) * NF + tid];
    }
    g_part[blockIdx.x * NF + tid] = (acc0 + acc1) + (acc2 + acc3);
}

// ---------------------------------------------------------------------------
// K4: reduce partials + leaky_relu -> g_cf  (1 block, 256 threads)
// ---------------------------------------------------------------------------
__global__ void k4_reduce() {
    const int f = threadIdx.x;
    float c = 0.f;
    #pragma unroll 8
    for (int b = 0; b < K3_BLOCKS; ++b) c += g_part[b * NF + f];
    g_cf[f] = (c > 0.f) ? c : 0.2f * c;
}

// ---------------------------------------------------------------------------
// K5: broadcast g_cf row to all 4096 output rows (float4 stores, 4 MB)
// ---------------------------------------------------------------------------
__global__ void k5_broadcast(float4* __restrict__ out) {
    const int idx = blockIdx.x * blockDim.x + threadIdx.x;  // 262144 float4s
    const float4 v = reinterpret_cast<const float4*>(g_cf)[idx & (NF / 4 - 1)];
    out[idx] = v;
}

// ---------------------------------------------------------------------------
extern "C" void kernel_launch(void* const* d_in, const int* in_sizes, int n_in,
                              void* d_out, int out_size) {
    const float* x = (const float*)d_in[0];   // (4096, 256) f32
    const float* W = (const float*)d_in[1];   // (4, 512) f32  (only W[:,256:] used)
    // d_in[2] = b, mathematically irrelevant (cancels in softmax)
    float* out = (float*)d_out;               // (4096, 256) f32

    k1_scores   <<<K1_BLOCKS, 256>>>(x, W);
    k3_partial  <<<K3_BLOCKS, 256>>>(x);
    k4_reduce   <<<1, 256>>>();
    k5_broadcast<<<(NROWS * NF / 4) / 256, 256>>>((float4*)out);
}

// round 2
// speedup vs baseline: 1.4775x; 1.4775x over previous
#include <cuda_runtime.h>
#include <cuda_bf16.h>

#define NROWS 4096
#define NF    256
#define NH    4
#define NB    128          // blocks; must be <= #SMs (148) for the spin barrier
#define TPB   256
#define RPB   (NROWS / NB) // 32 rows per block

// Scratch (__device__ globals per allocation-free rule)
__device__ float  g_tpart[NB * NH * NF];   // [b][h][f]  partial t sums, 512 KB
__device__ float4 g_dpart[NB];             // per-block d[h] partials
__device__ float  g_cf[NF];                // final broadcast row
__device__ unsigned g_cnt1, g_cnt2;        // monotonic barrier counters (replay-safe)

__device__ __forceinline__ void grid_sync(unsigned* cnt) {
    __threadfence();           // publish this thread's prior global writes
    __syncthreads();           // all threads of block have fenced
    if (threadIdx.x == 0) {
        unsigned old = atomicAdd(cnt, 1u);
        unsigned target = (old / NB + 1u) * NB;   // epoch end for THIS launch
        while (*(volatile unsigned*)cnt < target) { }
        __threadfence();       // acquire before reading peers' data
    }
    __syncthreads();
}

__global__ void __launch_bounds__(TPB, 1)
fused_mha(const float* __restrict__ x, const float* __restrict__ W,
          float* __restrict__ out)
{
    __shared__ float4 xs[RPB * (NF / 4)];   // 32 KB: this block's 32 rows of x
    __shared__ float4 w2s[NH][NF / 4];      // 4 KB:  W2 = W[:, 256:512]
    __shared__ float  es[RPB][NH];          // exp(scores) for this block's rows
    __shared__ float  sinv[NH];             // 1 / (H * d[h])
    __shared__ float  sT[8];                // phase-2 per-warp reduced T values

    const int tid  = threadIdx.x;
    const int lane = tid & 31, warp = tid >> 5;
    const int b    = blockIdx.x;
    const int rowbase = b * RPB;

    // ---- Phase 1: load tile, compute e, d_part, t_part ----------------------
    for (int i = tid; i < NH * (NF / 4); i += TPB) {
        int h = i >> 6, k = i & 63;
        w2s[h][k] = reinterpret_cast<const float4*>(W + h * 2 * NF + NF)[k];
    }
    const float4* xg = reinterpret_cast<const float4*>(x) + (size_t)rowbase * (NF / 4);
    #pragma unroll
    for (int i = 0; i < (RPB * NF / 4) / TPB; ++i)   // 8 coalesced float4 loads
        xs[tid + i * TPB] = xg[tid + i * TPB];
    __syncthreads();

    // scores + exp: 4 rows per warp (no max-subtraction: scores ~ N(0,0.16),
    // softmax is shift-invariant so this matches the reference exactly)
    for (int r = warp; r < RPB; r += 8) {
        float a0 = 0.f, a1 = 0.f, a2 = 0.f, a3 = 0.f;
        #pragma unroll
        for (int t = 0; t < 2; ++t) {
            const int k4 = lane + t * 32;
            const float4 xv = xs[r * (NF / 4) + k4];
            float4 w;
            w = w2s[0][k4]; a0 += xv.x*w.x + xv.y*w.y + xv.z*w.z + xv.w*w.w;
            w = w2s[1][k4]; a1 += xv.x*w.x + xv.y*w.y + xv.z*w.z + xv.w*w.w;
            w = w2s[2][k4]; a2 += xv.x*w.x + xv.y*w.y + xv.z*w.z + xv.w*w.w;
            w = w2s[3][k4]; a3 += xv.x*w.x + xv.y*w.y + xv.z*w.z + xv.w*w.w;
        }
        #pragma unroll
        for (int o = 16; o; o >>= 1) {
            a0 += __shfl_xor_sync(0xffffffffu, a0, o);
            a1 += __shfl_xor_sync(0xffffffffu, a1, o);
            a2 += __shfl_xor_sync(0xffffffffu, a2, o);
            a3 += __shfl_xor_sync(0xffffffffu, a3, o);
        }
        if (lane == 0) {
            es[r][0] = expf(a0); es[r][1] = expf(a1);
            es[r][2] = expf(a2); es[r][3] = expf(a3);
        }
    }
    __syncthreads();

    // per-block d[h] partial (fixed order)
    if (tid < NH) {
        float s = 0.f;
        #pragma unroll
        for (int r = 0; r < RPB; ++r) s += es[r][tid];
        ((float*)&g_dpart[b])[tid] = s;
    }
    // per-block t[h,f] partial; thread tid owns column f = tid
    {
        float t0 = 0.f, t1 = 0.f, t2 = 0.f, t3 = 0.f;
        const float* xsf = (const float*)xs;
        #pragma unroll
        for (int r = 0; r < RPB; ++r) {
            const float xv = xsf[r * NF + tid];
            t0 += es[r][0] * xv; t1 += es[r][1] * xv;
            t2 += es[r][2] * xv; t3 += es[r][3] * xv;
        }
        g_tpart[(b * NH + 0) * NF + tid] = t0;
        g_tpart[(b * NH + 1) * NF + tid] = t1;
        g_tpart[(b * NH + 2) * NF + tid] = t2;
        g_tpart[(b * NH + 3) * NF + tid] = t3;
    }

    grid_sync(&g_cnt1);

    // ---- Phase 2: distributed final reduce; block b produces f = 2b, 2b+1 ---
    if (warp == 0) {   // reduce d[h] (redundant per block would be wasteful; do here)
        float s0 = 0.f, s1 = 0.f, s2 = 0.f, s3 = 0.f;
        #pragma unroll
        for (int i = 0; i < 4; ++i) {
            float4 d = g_dpart[lane + i * 32];
            s0 += d.x; s1 += d.y; s2 += d.z; s3 += d.w;
        }
        #pragma unroll
        for (int o = 16; o; o >>= 1) {
            s0 += __shfl_xor_sync(0xffffffffu, s0, o);
            s1 += __shfl_xor_sync(0xffffffffu, s1, o);
            s2 += __shfl_xor_sync(0xffffffffu, s2, o);
            s3 += __shfl_xor_sync(0xffffffffu, s3, o);
        }
        if (lane == 0) {
            sinv[0] = 1.f / ((float)NH * s0);
            sinv[1] = 1.f / ((float)NH * s1);
            sinv[2] = 1.f / ((float)NH * s2);
            sinv[3] = 1.f / ((float)NH * s3);
        }
    }
    {   // warp w reduces T[h][f] for h = w&3, f = 2b + (w>>2)
        const int h = warp & 3;
        const int f = 2 * b + (warp >> 2);
        float s = 0.f;
        #pragma unroll
        for (int i = 0; i < 4; ++i)
            s += g_tpart[((lane + i * 32) * NH + h) * NF + f];
        #pragma unroll
        for (int o = 16; o; o >>= 1) s += __shfl_xor_sync(0xffffffffu, s, o);
        if (lane == 0) sT[warp] = s;
    }
    __syncthreads();
    if (tid < 2) {
        const int f = 2 * b + tid;
        float c = sinv[0] * sT[tid * 4 + 0] + sinv[1] * sT[tid * 4 + 1]
                + sinv[2] * sT[tid * 4 + 2] + sinv[3] * sT[tid * 4 + 3];
        g_cf[f] = (c > 0.f) ? c : 0.2f * c;   // leaky_relu(mean over heads)
    }

    grid_sync(&g_cnt2);

    // ---- Phase 3: broadcast final row to this block's 32 output rows --------
    const float4 v = reinterpret_cast<const float4*>(g_cf)[tid & 63];
    float4* og = reinterpret_cast<float4*>(out) + (size_t)rowbase * (NF / 4);
    #pragma unroll
    for (int i = 0; i < 8; ++i)
        og[tid + i * TPB] = v;
}

extern "C" void kernel_launch(void* const* d_in, const int* in_sizes, int n_in,
                              void* d_out, int out_size) {
    const float* x = (const float*)d_in[0];   // (4096, 256) f32
    const float* W = (const float*)d_in[1];   // (4, 512) f32; only W[:,256:] matters
    // d_in[2] = b: cancels inside softmax, mathematically irrelevant
    float* out = (float*)d_out;               // (4096, 256) f32

    fused_mha<<<NB, TPB>>>(x, W, out);
}